// round 7
// baseline (speedup 1.0000x reference)
#include <cuda_runtime.h>
#include <math.h>

#define TPB 640
#define NWARP 20
#define NBLK 148
#define TOTWARP (NBLK*NWARP)   // 2960
#define NRAYS 8192
#define LDW2 132
#define HSTR 132
#define GSTRIDE 1760
#define W2T_FLOATS (128*LDW2)
#define WSOFF W2T_FLOATS
#define GOFF (W2T_FLOATS + 2056)
#define SMEM_BYTES ((GOFF + NWARP*GSTRIDE)*4)

#define O_D    0
#define O_SDF  128
#define O_H1   256
#define O_WB   1312
#define O_CDF  1440
#define O_DF   1572
#define O_SF   1588
#define O_DM   1604
#define O_AUX  1732

typedef unsigned long long ull;

__device__ __forceinline__ ull fma2(ull a, ull b, ull c){
    ull d;
    asm("fma.rn.f32x2 %0, %1, %2, %3;" : "=l"(d) : "l"(a), "l"(b), "l"(c));
    return d;
}
__device__ __forceinline__ float lo32(ull v){ return __uint_as_float((unsigned)v); }
__device__ __forceinline__ float hi32(ull v){ return __uint_as_float((unsigned)(v>>32)); }

__device__ __forceinline__ float sigf(float x){
    return 1.0f/(1.0f + __expf(-x));
}

// One 8-point SDF MLP batch for THIS warp's ray. Warp-private.
// Per-ray layer-1 coefficients are recomputed here from staged weights
// (cheap: ~60 ops vs 2048 FFMA2) to keep cross-batch register pressure low.
__device__ __forceinline__ void sdf_batch(
    float* __restrict__ G, const float* __restrict__ W2T,
    const float* __restrict__ W1s, const float* __restrict__ b1s,
    const float* __restrict__ b2s, const float* __restrict__ W3s,
    float b3v,
    int din_off, int base, int sout_off, int lane)
{
    float* gh1 = G + O_H1;
    const float ox=G[O_AUX+0], oy=G[O_AUX+1], oz=G[O_AUX+2];
    const float dx=G[O_AUX+3], dy=G[O_AUX+4], dz=G[O_AUX+5];

    // layer 1 (coeffs recomputed, not kept live across batches)
    #pragma unroll
    for (int u=0; u<4; u++){
        int j = lane + 32*u;
        float wx=W1s[j], wy=W1s[128+j], wz=W1s[256+j];
        float c1 = dx*wx + dy*wy + dz*wz;
        float c0 = b1s[j] + ox*wx + oy*wy + oz*wz;
        #pragma unroll
        for (int pt=0; pt<8; pt++){
            float dv = G[din_off + base + pt];
            gh1[pt*HSTR + j] = fmaxf(fmaf(dv, c1, c0), 0.f);
        }
    }
    __syncwarp();

    ull acc[4][8];
    #pragma unroll
    for (int u=0; u<4; u++){
        float bv = b2s[lane + 32*u];
        #pragma unroll
        for (int p=0; p<8; p++)
            acc[u][p] = (ull)__float_as_uint(bv);
    }

    const ulonglong2* w0 = (const ulonglong2*)(W2T + (lane      )*LDW2);
    const ulonglong2* w1 = (const ulonglong2*)(W2T + (lane + 32 )*LDW2);
    const ulonglong2* w2r= (const ulonglong2*)(W2T + (lane + 64 )*LDW2);
    const ulonglong2* w3r= (const ulonglong2*)(W2T + (lane + 96 )*LDW2);

    #pragma unroll 4
    for (int k4=0; k4<32; k4++){
        ulonglong2 wv[4];
        wv[0]=w0[k4]; wv[1]=w1[k4]; wv[2]=w2r[k4]; wv[3]=w3r[k4];
        #pragma unroll
        for (int p=0; p<8; p++){
            ulonglong2 hv = *(const ulonglong2*)(gh1 + p*HSTR + k4*4);
            acc[0][p] = fma2(wv[0].x, hv.x, acc[0][p]);
            acc[0][p] = fma2(wv[0].y, hv.y, acc[0][p]);
            acc[1][p] = fma2(wv[1].x, hv.x, acc[1][p]);
            acc[1][p] = fma2(wv[1].y, hv.y, acc[1][p]);
            acc[2][p] = fma2(wv[2].x, hv.x, acc[2][p]);
            acc[2][p] = fma2(wv[2].y, hv.y, acc[2][p]);
            acc[3][p] = fma2(wv[3].x, hv.x, acc[3][p]);
            acc[3][p] = fma2(wv[3].y, hv.y, acc[3][p]);
        }
    }

    float w3v[4];
    #pragma unroll
    for (int u=0; u<4; u++) w3v[u] = W3s[lane + 32*u];

    #pragma unroll
    for (int pt=0; pt<8; pt++){
        float t = 0.f;
        #pragma unroll
        for (int u=0; u<4; u++){
            float f = lo32(acc[u][pt]) + hi32(acc[u][pt]);
            t += fmaxf(f, 0.f) * w3v[u];
        }
        #pragma unroll
        for (int o=16;o;o>>=1) t += __shfl_down_sync(0xffffffffu, t, o);
        if (lane == 0) G[sout_off + base + pt] = t + b3v;
    }
    __syncwarp();
}

__global__ void __launch_bounds__(TPB,1) neus_kernel(
    const float* __restrict__ rays_o, const float* __restrict__ rays_d,
    const float* __restrict__ W1, const float* __restrict__ b1,
    const float* __restrict__ W2, const float* __restrict__ b2,
    const float* __restrict__ W3, const float* __restrict__ b3,
    const float* __restrict__ R1, const float* __restrict__ r1,
    const float* __restrict__ R2, const float* __restrict__ r2,
    const float* __restrict__ s_val, float* __restrict__ out)
{
    extern __shared__ float sm[];
    float* W2T = sm;
    float* WS  = sm + WSOFF;
    float* W1s = WS;         // 384
    float* b1s = WS+384;     // 128
    float* b2s = WS+512;     // 128
    float* W3s = WS+640;     // 128
    float* R1s = WS+768;     // 768
    float* r1s = WS+1536;    // 128
    float* F0  = WS+1664;    // 128 (R2 col 0)
    float* F1  = WS+1792;    // 128
    float* F2  = WS+1920;    // 128
    float* r2s = WS+2048;    // 3
    float* b3p = WS+2051;
    float* scp = WS+2052;

    const int tid  = threadIdx.x;
    const int w    = tid >> 5;
    const int lane = tid & 31;
    const unsigned FULL = 0xffffffffu;

    // ---- stage weights once per SM ----
    for (int idx=tid; idx<128*128; idx+=TPB){
        int k = idx >> 7, jj = idx & 127;
        W2T[jj*LDW2 + k] = W2[idx];
    }
    for (int idx=tid; idx<384; idx+=TPB) W1s[idx] = W1[idx];
    for (int idx=tid; idx<128; idx+=TPB){
        b1s[idx]=b1[idx]; b2s[idx]=b2[idx]; W3s[idx]=W3[idx]; r1s[idx]=r1[idx];
        F0[idx]=R2[3*idx]; F1[idx]=R2[3*idx+1]; F2[idx]=R2[3*idx+2];
    }
    for (int idx=tid; idx<768; idx+=TPB) R1s[idx] = R1[idx];
    if (tid < 3) r2s[tid] = r2[tid];
    if (tid == 0){ b3p[0] = b3[0]; scp[0] = s_val[0]*64.0f; }
    __syncthreads();

    float* G = sm + GOFF + w*GSTRIDE;
    const int gw = blockIdx.x*NWARP + w;
    const float b3v = b3p[0];

    for (int ri=0; ri<3; ri++){
        const int ray = gw + ri*TOTWARP;
        if (ray >= NRAYS) break;

        if (lane == 0){
            float oxl=rays_o[ray*3+0], oyl=rays_o[ray*3+1], ozl=rays_o[ray*3+2];
            float ddx=rays_d[ray*3+0], ddy=rays_d[ray*3+1], ddz=rays_d[ray*3+2];
            float nrm = sqrtf(ddx*ddx+ddy*ddy+ddz*ddz);
            G[O_AUX+0]=oxl; G[O_AUX+1]=oyl; G[O_AUX+2]=ozl;
            G[O_AUX+3]=ddx/nrm; G[O_AUX+4]=ddy/nrm; G[O_AUX+5]=ddz/nrm;
        }
        #pragma unroll
        for (int e=lane; e<64; e+=32){
            float t = (e==63) ? 1.0f : (float)e * (1.0f/63.0f);
            G[O_D + e] = 0.5f*(1.0f-t) + 4.0f*t;
        }
        __syncwarp();

        // ---- coarse SDF ----
        for (int b=0;b<8;b++)
            sdf_batch(G, W2T, W1s,b1s,b2s,W3s, b3v, O_D, b*8, O_SDF, lane);

        // ---- hierarchical upsampling ----
        int n = 64;
        for (int it=0; it<4; it++){
            float s_i = 64.0f * (float)(1<<it);
            #pragma unroll
            for (int e=lane; e<128; e+=32){
                float val = 0.0f;
                if (e < n-1){
                    float psdf=G[O_SDF+e], nsdf=G[O_SDF+e+1], pz=G[O_D+e], nz=G[O_D+e+1];
                    float dot = (nsdf-psdf)/(nz-pz+1e-5f);
                    float pdot = 0.0f;
                    if (e > 0){
                        float ppsdf=G[O_SDF+e-1], ppz=G[O_D+e-1];
                        pdot = (psdf-ppsdf)/(pz-ppz+1e-5f);
                    }
                    float dc = fminf(fmaxf(fminf(pdot,dot),-10.0f),0.0f);
                    float mid = 0.5f*(psdf+nsdf), dist = nz-pz;
                    float pc = sigf((mid - dc*dist*0.5f)*s_i);
                    float nc = sigf((mid + dc*dist*0.5f)*s_i);
                    val = (pc-nc+1e-5f)/(pc+1e-5f);
                }
                G[O_WB+e] = val;
            }
            __syncwarp();

            // warp scan: w = a*T + 1e-5 ; cdf = cumsum(w)/sum
            {
                float4 av = *(const float4*)(G + O_WB + 4*lane);
                float a[4] = {av.x, av.y, av.z, av.w};
                float sh[4], Tl[4], wv4[4];
                #pragma unroll
                for (int r=0;r<4;r++){
                    int e = 4*lane + r;
                    sh[r] = (e < n-1) ? (1.0f - a[r] + 1e-10f) : 1.0f;
                }
                Tl[0]=1.0f; Tl[1]=sh[0]; Tl[2]=sh[0]*sh[1]; Tl[3]=Tl[2]*sh[2];
                float P = Tl[3]*sh[3];
                float v = P;
                #pragma unroll
                for (int o=1;o<32;o<<=1){
                    float t = __shfl_up_sync(FULL, v, o);
                    if (lane >= o) v *= t;
                }
                float exc = __shfl_up_sync(FULL, v, 1);
                if (lane == 0) exc = 1.0f;
                float lsum = 0.f;
                #pragma unroll
                for (int r=0;r<4;r++){
                    int e = 4*lane + r;
                    wv4[r] = (e < n-1) ? fmaf(a[r], exc*Tl[r], 1e-5f) : 0.0f;
                    lsum += wv4[r];
                }
                float va = lsum;
                #pragma unroll
                for (int o=1;o<32;o<<=1){
                    float t = __shfl_up_sync(FULL, va, o);
                    if (lane >= o) va += t;
                }
                float total = __shfl_sync(FULL, va, 31);
                float inv = 1.0f/total;
                float base = va - lsum;
                float run = 0.f;
                #pragma unroll
                for (int r=0;r<4;r++){
                    run += wv4[r];
                    G[O_CDF + 4*lane + 1 + r] = (base + run)*inv;
                }
                if (lane == 0) G[O_CDF] = 0.0f;
            }
            __syncwarp();

            if (lane < 16){
                float u = (lane==15) ? 1.0f : (float)lane * (1.0f/15.0f);
                int lo = 0, hi = n;
                #pragma unroll
                for (int s7=0; s7<7; s7++){
                    int mid = (lo+hi) >> 1;
                    if (G[O_CDF+mid] <= u) lo = mid+1; else hi = mid;
                }
                int ind = lo;
                int below = ind-1; if (below < 0) below = 0; if (below > n-1) below = n-1;
                int above = (ind < n-1) ? ind : n-1;
                float cb=G[O_CDF+below], ca=G[O_CDF+above];
                float bb=G[O_D+below],  ba=G[O_D+above];
                float den = ca-cb; if (den < 1e-5f) den = 1.0f;
                float tt = (u-cb)/den;
                G[O_DF+lane] = bb + tt*(ba-bb);
            }
            __syncwarp();

            sdf_batch(G, W2T, W1s,b1s,b2s,W3s, b3v, O_DF, 0, O_SF, lane);
            sdf_batch(G, W2T, W1s,b1s,b2s,W3s, b3v, O_DF, 8, O_SF, lane);

            // ---- parallel stable merge via ranks ----
            {
                float dv[4], sv[4]; int rk[4];
                #pragma unroll
                for (int m=0;m<4;m++){
                    int e = lane + 32*m;
                    rk[m] = -1;
                    if (e < n){
                        dv[m]=G[O_D+e]; sv[m]=G[O_SDF+e];
                        int lo=0, hi=16;
                        #pragma unroll
                        for (int s5=0;s5<5;s5++){
                            int mid=(lo+hi)>>1;
                            if (mid < 16 && G[O_DF+mid] < dv[m]) lo=mid+1; else hi=mid;
                        }
                        rk[m] = e + lo;
                    }
                }
                float bf=0.f, bsf=0.f; int rkf=-1;
                if (lane < 16){
                    bf=G[O_DF+lane]; bsf=G[O_SF+lane];
                    int lo=0, hi=n;
                    #pragma unroll
                    for (int s7=0;s7<7;s7++){
                        int mid=(lo+hi)>>1;
                        if (mid < n && G[O_D+mid] <= bf) lo=mid+1; else hi=mid;
                    }
                    rkf = lane + lo;
                }
                __syncwarp();
                #pragma unroll
                for (int m=0;m<4;m++){
                    if (rk[m] >= 0){ G[O_D+rk[m]]=dv[m]; G[O_SDF+rk[m]]=sv[m]; }
                }
                if (rkf >= 0){ G[O_D+rkf]=bf; G[O_SDF+rkf]=bsf; }
            }
            __syncwarp();
            n += 16;
        }

        // ---- final compositing (n==128) ----
        const float ox=G[O_AUX+0], oy=G[O_AUX+1], oz=G[O_AUX+2];
        const float dx=G[O_AUX+3], dy=G[O_AUX+4], dz=G[O_AUX+5];
        const float s = scp[0];
        #pragma unroll
        for (int e=lane; e<128; e+=32) G[O_CDF+e] = sigf(G[O_SDF+e]*s);
        #pragma unroll
        for (int e=lane; e<128; e+=32) G[O_DM+e] = (e<127) ? 0.5f*(G[O_D+e]+G[O_D+e+1]) : 0.0f;
        __syncwarp();
        #pragma unroll
        for (int e=lane; e<128; e+=32){
            float val = 0.0f;
            if (e < 127){
                float a = (G[O_CDF+e]-G[O_CDF+e+1]+1e-5f)/(G[O_CDF+e]+1e-5f);
                val = fminf(fmaxf(a,0.0f),1.0f);
            }
            G[O_WB+e] = val;
        }
        __syncwarp();

        float wv4[4], dm4[4];
        {
            float4 av = *(const float4*)(G + O_WB + 4*lane);
            float4 dmv= *(const float4*)(G + O_DM + 4*lane);
            float a[4] = {av.x, av.y, av.z, av.w};
            dm4[0]=dmv.x; dm4[1]=dmv.y; dm4[2]=dmv.z; dm4[3]=dmv.w;
            float sh[4], Tl[4];
            #pragma unroll
            for (int r=0;r<4;r++){
                int e = 4*lane + r;
                sh[r] = (e < 127) ? (1.0f - a[r] + 1e-10f) : 1.0f;
            }
            Tl[0]=1.0f; Tl[1]=sh[0]; Tl[2]=sh[0]*sh[1]; Tl[3]=Tl[2]*sh[2];
            float P = Tl[3]*sh[3];
            float v = P;
            #pragma unroll
            for (int o=1;o<32;o<<=1){
                float t = __shfl_up_sync(FULL, v, o);
                if (lane >= o) v *= t;
            }
            float exc = __shfl_up_sync(FULL, v, 1);
            if (lane == 0) exc = 1.0f;
            #pragma unroll
            for (int r=0;r<4;r++){
                int e = 4*lane + r;
                wv4[r] = (e < 127) ? a[r]*exc*Tl[r] : 0.0f;
            }
        }

        // ---- radiance: per-ray A0/A1 staging, flipped loop ----
        float* A0 = G + O_H1;
        float* A1 = G + O_H1 + 128;
        #pragma unroll
        for (int u=0; u<4; u++){
            int j = lane + 32*u;
            float c1r = dx*R1s[j] + dy*R1s[128+j] + dz*R1s[256+j];
            float c0r = r1s[j] + ox*R1s[j] + oy*R1s[128+j] + oz*R1s[256+j]
                      + dx*R1s[384+j] + dy*R1s[512+j] + dz*R1s[640+j];
            A0[j]=c0r; A1[j]=c1r;
        }
        __syncwarp();

        float t0[4]={0,0,0,0}, t1[4]={0,0,0,0}, t2[4]={0,0,0,0};
        #pragma unroll 2
        for (int k4=0; k4<32; k4++){
            float4 C0=*(const float4*)(A0+4*k4);
            float4 C1=*(const float4*)(A1+4*k4);
            float4 G0=*(const float4*)(F0+4*k4);
            float4 G1=*(const float4*)(F1+4*k4);
            float4 G2=*(const float4*)(F2+4*k4);
            const float c0k[4]={C0.x,C0.y,C0.z,C0.w};
            const float c1k[4]={C1.x,C1.y,C1.z,C1.w};
            const float f0k[4]={G0.x,G0.y,G0.z,G0.w};
            const float f1k[4]={G1.x,G1.y,G1.z,G1.w};
            const float f2k[4]={G2.x,G2.y,G2.z,G2.w};
            #pragma unroll
            for (int kk=0;kk<4;kk++){
                #pragma unroll
                for (int r=0;r<4;r++){
                    float h = fmaxf(fmaf(dm4[r], c1k[kk], c0k[kk]), 0.f);
                    t0[r] = fmaf(h, f0k[kk], t0[r]);
                    t1[r] = fmaf(h, f1k[kk], t1[r]);
                    t2[r] = fmaf(h, f2k[kk], t2[r]);
                }
            }
        }

        const float r2c0=r2s[0], r2c1=r2s[1], r2c2=r2s[2];
        float rgb0=0.f, rgb1=0.f, rgb2=0.f, dep=0.f, ac=0.f;
        #pragma unroll
        for (int r=0;r<4;r++){
            float wvv = wv4[r];
            rgb0 = fmaf(wvv, sigf(t0[r]+r2c0), rgb0);
            rgb1 = fmaf(wvv, sigf(t1[r]+r2c1), rgb1);
            rgb2 = fmaf(wvv, sigf(t2[r]+r2c2), rgb2);
            dep  = fmaf(wvv, dm4[r], dep);
            ac  += wvv;
        }
        #pragma unroll
        for (int o=16;o;o>>=1){
            rgb0 += __shfl_down_sync(FULL, rgb0, o);
            rgb1 += __shfl_down_sync(FULL, rgb1, o);
            rgb2 += __shfl_down_sync(FULL, rgb2, o);
            dep  += __shfl_down_sync(FULL, dep, o);
            ac   += __shfl_down_sync(FULL, ac, o);
        }
        if (lane == 0){
            out[ray*5+0]=rgb0;
            out[ray*5+1]=rgb1;
            out[ray*5+2]=rgb2;
            out[ray*5+3]=dep;
            out[ray*5+4]=ac;
        }
        __syncwarp();
    }
}

extern "C" void kernel_launch(void* const* d_in, const int* in_sizes, int n_in,
                              void* d_out, int out_size)
{
    const float* rays_o = (const float*)d_in[0];
    const float* rays_d = (const float*)d_in[1];
    const float* W1 = (const float*)d_in[2];
    const float* b1 = (const float*)d_in[3];
    const float* W2 = (const float*)d_in[4];
    const float* b2 = (const float*)d_in[5];
    const float* W3 = (const float*)d_in[6];
    const float* b3 = (const float*)d_in[7];
    const float* R1 = (const float*)d_in[8];
    const float* r1 = (const float*)d_in[9];
    const float* R2 = (const float*)d_in[10];
    const float* r2 = (const float*)d_in[11];
    const float* sv = (const float*)d_in[12];
    float* out = (float*)d_out;

    cudaFuncSetAttribute(neus_kernel, cudaFuncAttributeMaxDynamicSharedMemorySize, SMEM_BYTES);
    neus_kernel<<<NBLK, TPB, SMEM_BYTES>>>(rays_o,rays_d,W1,b1,W2,b2,W3,b3,R1,r1,R2,r2,sv,out);
}

// round 8
// speedup vs baseline: 1.1196x; 1.1196x over previous
#include <cuda_runtime.h>
#include <math.h>

#define TPB 512
#define RAYS 16
#define LDW2 132
#define HSTR 132
#define GSTRIDE 1760
#define W2T_FLOATS (128*LDW2)
#define WSOFF W2T_FLOATS
#define GOFF (W2T_FLOATS + 2056)
#define SMEM_BYTES ((GOFF + RAYS*GSTRIDE)*4)

#define O_D    0
#define O_SDF  128
#define O_H1   256
#define O_WB   1312
#define O_CDF  1440
#define O_DF   1572
#define O_SF   1588
#define O_DM   1604
#define O_AUX  1732

typedef unsigned long long ull;

__device__ __forceinline__ ull fma2(ull a, ull b, ull c){
    ull d;
    asm("fma.rn.f32x2 %0, %1, %2, %3;" : "=l"(d) : "l"(a), "l"(b), "l"(c));
    return d;
}
__device__ __forceinline__ float lo32(ull v){ return __uint_as_float((unsigned)v); }
__device__ __forceinline__ float hi32(ull v){ return __uint_as_float((unsigned)(v>>32)); }

__device__ __forceinline__ float sigf(float x){
    return 1.0f/(1.0f + __expf(-x));
}

// One 8-point SDF MLP batch for THIS warp's ray. Warp-private.
// Software-pipelined k-loop: W double-buffered one k4 ahead, h streamed with
// a 2-point-ahead rotating buffer. Out-of-range prefetches land in the
// LDW2/HSTR=132 row padding (in-bounds, never consumed).
__device__ __forceinline__ void sdf_batch(
    float* __restrict__ G, const float* __restrict__ W2T,
    const float* __restrict__ W1s, const float* __restrict__ b1s,
    const float* __restrict__ b2s, const float* __restrict__ W3s,
    float b3v,
    int din_off, int base, int sout_off, int lane)
{
    float* gh1 = G + O_H1;
    const float ox=G[O_AUX+0], oy=G[O_AUX+1], oz=G[O_AUX+2];
    const float dx=G[O_AUX+3], dy=G[O_AUX+4], dz=G[O_AUX+5];

    // layer 1 (coeffs recomputed per batch to keep cross-batch regs low)
    #pragma unroll
    for (int u=0; u<4; u++){
        int j = lane + 32*u;
        float wx=W1s[j], wy=W1s[128+j], wz=W1s[256+j];
        float c1 = dx*wx + dy*wy + dz*wz;
        float c0 = b1s[j] + ox*wx + oy*wy + oz*wz;
        #pragma unroll
        for (int pt=0; pt<8; pt++){
            float dv = G[din_off + base + pt];
            gh1[pt*HSTR + j] = fmaxf(fmaf(dv, c1, c0), 0.f);
        }
    }
    __syncwarp();

    ull acc[4][8];
    #pragma unroll
    for (int u=0; u<4; u++){
        float bv = b2s[lane + 32*u];
        #pragma unroll
        for (int p=0; p<8; p++)
            acc[u][p] = (ull)__float_as_uint(bv);
    }

    const ulonglong2* w0 = (const ulonglong2*)(W2T + (lane      )*LDW2);
    const ulonglong2* w1 = (const ulonglong2*)(W2T + (lane + 32 )*LDW2);
    const ulonglong2* w2r= (const ulonglong2*)(W2T + (lane + 64 )*LDW2);
    const ulonglong2* w3r= (const ulonglong2*)(W2T + (lane + 96 )*LDW2);

    // prime the pipeline
    ulonglong2 wv0=w0[0], wv1=w1[0], wv2=w2r[0], wv3=w3r[0];
    ulonglong2 hvA = *(const ulonglong2*)(gh1 + 0*HSTR + 0);
    ulonglong2 hvB = *(const ulonglong2*)(gh1 + 1*HSTR + 0);

    #pragma unroll 4
    for (int k4=0; k4<32; k4++){
        // prefetch next k4's W (k4=31 reads row padding: in-bounds, unused)
        ulonglong2 wn0=w0[k4+1], wn1=w1[k4+1], wn2=w2r[k4+1], wn3=w3r[k4+1];
        #pragma unroll
        for (int p=0; p<8; p++){
            ulonglong2 hv = (p & 1) ? hvB : hvA;
            // prefetch h for (k4, p+2) or (k4+1, p-6)
            const float* naddr = (p+2 < 8)
                ? (gh1 + (p+2)*HSTR + k4*4)
                : (gh1 + (p-6)*HSTR + (k4+1)*4);
            if (p & 1) hvB = *(const ulonglong2*)naddr;
            else       hvA = *(const ulonglong2*)naddr;

            acc[0][p] = fma2(wv0.x, hv.x, acc[0][p]);
            acc[0][p] = fma2(wv0.y, hv.y, acc[0][p]);
            acc[1][p] = fma2(wv1.x, hv.x, acc[1][p]);
            acc[1][p] = fma2(wv1.y, hv.y, acc[1][p]);
            acc[2][p] = fma2(wv2.x, hv.x, acc[2][p]);
            acc[2][p] = fma2(wv2.y, hv.y, acc[2][p]);
            acc[3][p] = fma2(wv3.x, hv.x, acc[3][p]);
            acc[3][p] = fma2(wv3.y, hv.y, acc[3][p]);
        }
        wv0=wn0; wv1=wn1; wv2=wn2; wv3=wn3;
    }

    float w3v[4];
    #pragma unroll
    for (int u=0; u<4; u++) w3v[u] = W3s[lane + 32*u];

    #pragma unroll
    for (int pt=0; pt<8; pt++){
        float t = 0.f;
        #pragma unroll
        for (int u=0; u<4; u++){
            float f = lo32(acc[u][pt]) + hi32(acc[u][pt]);
            t += fmaxf(f, 0.f) * w3v[u];
        }
        #pragma unroll
        for (int o=16;o;o>>=1) t += __shfl_down_sync(0xffffffffu, t, o);
        if (lane == 0) G[sout_off + base + pt] = t + b3v;
    }
    __syncwarp();
}

__global__ void __launch_bounds__(TPB,1) neus_kernel(
    const float* __restrict__ rays_o, const float* __restrict__ rays_d,
    const float* __restrict__ W1, const float* __restrict__ b1,
    const float* __restrict__ W2, const float* __restrict__ b2,
    const float* __restrict__ W3, const float* __restrict__ b3,
    const float* __restrict__ R1, const float* __restrict__ r1,
    const float* __restrict__ R2, const float* __restrict__ r2,
    const float* __restrict__ s_val, float* __restrict__ out)
{
    extern __shared__ float sm[];
    float* W2T = sm;
    float* WS  = sm + WSOFF;
    float* W1s = WS;         // 384
    float* b1s = WS+384;     // 128
    float* b2s = WS+512;     // 128
    float* W3s = WS+640;     // 128
    float* R1s = WS+768;     // 768
    float* r1s = WS+1536;    // 128
    float* F0  = WS+1664;    // 128 (R2 col 0)
    float* F1  = WS+1792;    // 128
    float* F2  = WS+1920;    // 128
    float* r2s = WS+2048;    // 3
    float* b3p = WS+2051;
    float* scp = WS+2052;

    const int tid  = threadIdx.x;
    const int w    = tid >> 5;
    const int lane = tid & 31;
    const int ray  = blockIdx.x*RAYS + w;
    const unsigned FULL = 0xffffffffu;

    // ---- stage weights ----
    for (int idx=tid; idx<128*128; idx+=TPB){
        int k = idx >> 7, jj = idx & 127;
        W2T[jj*LDW2 + k] = W2[idx];
    }
    for (int idx=tid; idx<384; idx+=TPB) W1s[idx] = W1[idx];
    for (int idx=tid; idx<128; idx+=TPB){
        b1s[idx]=b1[idx]; b2s[idx]=b2[idx]; W3s[idx]=W3[idx]; r1s[idx]=r1[idx];
        F0[idx]=R2[3*idx]; F1[idx]=R2[3*idx+1]; F2[idx]=R2[3*idx+2];
    }
    for (int idx=tid; idx<768; idx+=TPB) R1s[idx] = R1[idx];
    if (tid < 3) r2s[tid] = r2[tid];
    if (tid == 0){ b3p[0] = b3[0]; scp[0] = s_val[0]*64.0f; }
    __syncthreads();

    float* G = sm + GOFF + w*GSTRIDE;
    const float b3v = b3p[0];

    if (lane == 0){
        float oxl=rays_o[ray*3+0], oyl=rays_o[ray*3+1], ozl=rays_o[ray*3+2];
        float ddx=rays_d[ray*3+0], ddy=rays_d[ray*3+1], ddz=rays_d[ray*3+2];
        float nrm = sqrtf(ddx*ddx+ddy*ddy+ddz*ddz);
        G[O_AUX+0]=oxl; G[O_AUX+1]=oyl; G[O_AUX+2]=ozl;
        G[O_AUX+3]=ddx/nrm; G[O_AUX+4]=ddy/nrm; G[O_AUX+5]=ddz/nrm;
    }
    #pragma unroll
    for (int e=lane; e<64; e+=32){
        float t = (e==63) ? 1.0f : (float)e * (1.0f/63.0f);
        G[O_D + e] = 0.5f*(1.0f-t) + 4.0f*t;
    }
    __syncwarp();

    // ---- coarse SDF ----
    for (int b=0;b<8;b++)
        sdf_batch(G, W2T, W1s,b1s,b2s,W3s, b3v, O_D, b*8, O_SDF, lane);

    // ---- hierarchical upsampling ----
    int n = 64;
    for (int it=0; it<4; it++){
        float s_i = 64.0f * (float)(1<<it);
        #pragma unroll
        for (int e=lane; e<128; e+=32){
            float val = 0.0f;
            if (e < n-1){
                float psdf=G[O_SDF+e], nsdf=G[O_SDF+e+1], pz=G[O_D+e], nz=G[O_D+e+1];
                float dot = (nsdf-psdf)/(nz-pz+1e-5f);
                float pdot = 0.0f;
                if (e > 0){
                    float ppsdf=G[O_SDF+e-1], ppz=G[O_D+e-1];
                    pdot = (psdf-ppsdf)/(pz-ppz+1e-5f);
                }
                float dc = fminf(fmaxf(fminf(pdot,dot),-10.0f),0.0f);
                float mid = 0.5f*(psdf+nsdf), dist = nz-pz;
                float pc = sigf((mid - dc*dist*0.5f)*s_i);
                float nc = sigf((mid + dc*dist*0.5f)*s_i);
                val = (pc-nc+1e-5f)/(pc+1e-5f);
            }
            G[O_WB+e] = val;
        }
        __syncwarp();

        // warp scan: w = a*T + 1e-5 ; cdf = cumsum(w)/sum
        {
            float4 av = *(const float4*)(G + O_WB + 4*lane);
            float a[4] = {av.x, av.y, av.z, av.w};
            float sh[4], Tl[4], wv4[4];
            #pragma unroll
            for (int r=0;r<4;r++){
                int e = 4*lane + r;
                sh[r] = (e < n-1) ? (1.0f - a[r] + 1e-10f) : 1.0f;
            }
            Tl[0]=1.0f; Tl[1]=sh[0]; Tl[2]=sh[0]*sh[1]; Tl[3]=Tl[2]*sh[2];
            float P = Tl[3]*sh[3];
            float v = P;
            #pragma unroll
            for (int o=1;o<32;o<<=1){
                float t = __shfl_up_sync(FULL, v, o);
                if (lane >= o) v *= t;
            }
            float exc = __shfl_up_sync(FULL, v, 1);
            if (lane == 0) exc = 1.0f;
            float lsum = 0.f;
            #pragma unroll
            for (int r=0;r<4;r++){
                int e = 4*lane + r;
                wv4[r] = (e < n-1) ? fmaf(a[r], exc*Tl[r], 1e-5f) : 0.0f;
                lsum += wv4[r];
            }
            float va = lsum;
            #pragma unroll
            for (int o=1;o<32;o<<=1){
                float t = __shfl_up_sync(FULL, va, o);
                if (lane >= o) va += t;
            }
            float total = __shfl_sync(FULL, va, 31);
            float inv = 1.0f/total;
            float base = va - lsum;
            float run = 0.f;
            #pragma unroll
            for (int r=0;r<4;r++){
                run += wv4[r];
                G[O_CDF + 4*lane + 1 + r] = (base + run)*inv;
            }
            if (lane == 0) G[O_CDF] = 0.0f;
        }
        __syncwarp();

        if (lane < 16){
            float u = (lane==15) ? 1.0f : (float)lane * (1.0f/15.0f);
            int lo = 0, hi = n;
            #pragma unroll
            for (int s7=0; s7<7; s7++){
                int mid = (lo+hi) >> 1;
                if (G[O_CDF+mid] <= u) lo = mid+1; else hi = mid;
            }
            int ind = lo;
            int below = ind-1; if (below < 0) below = 0; if (below > n-1) below = n-1;
            int above = (ind < n-1) ? ind : n-1;
            float cb=G[O_CDF+below], ca=G[O_CDF+above];
            float bb=G[O_D+below],  ba=G[O_D+above];
            float den = ca-cb; if (den < 1e-5f) den = 1.0f;
            float tt = (u-cb)/den;
            G[O_DF+lane] = bb + tt*(ba-bb);
        }
        __syncwarp();

        sdf_batch(G, W2T, W1s,b1s,b2s,W3s, b3v, O_DF, 0, O_SF, lane);
        sdf_batch(G, W2T, W1s,b1s,b2s,W3s, b3v, O_DF, 8, O_SF, lane);

        // ---- parallel stable merge via ranks ----
        {
            float dv[4], sv[4]; int rk[4];
            #pragma unroll
            for (int m=0;m<4;m++){
                int e = lane + 32*m;
                rk[m] = -1;
                if (e < n){
                    dv[m]=G[O_D+e]; sv[m]=G[O_SDF+e];
                    int lo=0, hi=16;
                    #pragma unroll
                    for (int s5=0;s5<5;s5++){
                        int mid=(lo+hi)>>1;
                        if (mid < 16 && G[O_DF+mid] < dv[m]) lo=mid+1; else hi=mid;
                    }
                    rk[m] = e + lo;
                }
            }
            float bf=0.f, bsf=0.f; int rkf=-1;
            if (lane < 16){
                bf=G[O_DF+lane]; bsf=G[O_SF+lane];
                int lo=0, hi=n;
                #pragma unroll
                for (int s7=0;s7<7;s7++){
                    int mid=(lo+hi)>>1;
                    if (mid < n && G[O_D+mid] <= bf) lo=mid+1; else hi=mid;
                }
                rkf = lane + lo;
            }
            __syncwarp();
            #pragma unroll
            for (int m=0;m<4;m++){
                if (rk[m] >= 0){ G[O_D+rk[m]]=dv[m]; G[O_SDF+rk[m]]=sv[m]; }
            }
            if (rkf >= 0){ G[O_D+rkf]=bf; G[O_SDF+rkf]=bsf; }
        }
        __syncwarp();
        n += 16;
    }

    // ---- final compositing (n==128) ----
    const float ox=G[O_AUX+0], oy=G[O_AUX+1], oz=G[O_AUX+2];
    const float dx=G[O_AUX+3], dy=G[O_AUX+4], dz=G[O_AUX+5];
    const float s = scp[0];
    #pragma unroll
    for (int e=lane; e<128; e+=32) G[O_CDF+e] = sigf(G[O_SDF+e]*s);
    #pragma unroll
    for (int e=lane; e<128; e+=32) G[O_DM+e] = (e<127) ? 0.5f*(G[O_D+e]+G[O_D+e+1]) : 0.0f;
    __syncwarp();
    #pragma unroll
    for (int e=lane; e<128; e+=32){
        float val = 0.0f;
        if (e < 127){
            float a = (G[O_CDF+e]-G[O_CDF+e+1]+1e-5f)/(G[O_CDF+e]+1e-5f);
            val = fminf(fmaxf(a,0.0f),1.0f);
        }
        G[O_WB+e] = val;
    }
    __syncwarp();

    float wv4[4], dm4[4];
    {
        float4 av = *(const float4*)(G + O_WB + 4*lane);
        float4 dmv= *(const float4*)(G + O_DM + 4*lane);
        float a[4] = {av.x, av.y, av.z, av.w};
        dm4[0]=dmv.x; dm4[1]=dmv.y; dm4[2]=dmv.z; dm4[3]=dmv.w;
        float sh[4], Tl[4];
        #pragma unroll
        for (int r=0;r<4;r++){
            int e = 4*lane + r;
            sh[r] = (e < 127) ? (1.0f - a[r] + 1e-10f) : 1.0f;
        }
        Tl[0]=1.0f; Tl[1]=sh[0]; Tl[2]=sh[0]*sh[1]; Tl[3]=Tl[2]*sh[2];
        float P = Tl[3]*sh[3];
        float v = P;
        #pragma unroll
        for (int o=1;o<32;o<<=1){
            float t = __shfl_up_sync(FULL, v, o);
            if (lane >= o) v *= t;
        }
        float exc = __shfl_up_sync(FULL, v, 1);
        if (lane == 0) exc = 1.0f;
        #pragma unroll
        for (int r=0;r<4;r++){
            int e = 4*lane + r;
            wv4[r] = (e < 127) ? a[r]*exc*Tl[r] : 0.0f;
        }
    }

    // ---- radiance: per-ray A0/A1 staging, flipped loop ----
    float* A0 = G + O_H1;
    float* A1 = G + O_H1 + 128;
    #pragma unroll
    for (int u=0; u<4; u++){
        int j = lane + 32*u;
        float c1r = dx*R1s[j] + dy*R1s[128+j] + dz*R1s[256+j];
        float c0r = r1s[j] + ox*R1s[j] + oy*R1s[128+j] + oz*R1s[256+j]
                  + dx*R1s[384+j] + dy*R1s[512+j] + dz*R1s[640+j];
        A0[j]=c0r; A1[j]=c1r;
    }
    __syncwarp();

    float t0[4]={0,0,0,0}, t1[4]={0,0,0,0}, t2[4]={0,0,0,0};
    #pragma unroll 2
    for (int k4=0; k4<32; k4++){
        float4 C0=*(const float4*)(A0+4*k4);
        float4 C1=*(const float4*)(A1+4*k4);
        float4 G0=*(const float4*)(F0+4*k4);
        float4 G1=*(const float4*)(F1+4*k4);
        float4 G2=*(const float4*)(F2+4*k4);
        const float c0k[4]={C0.x,C0.y,C0.z,C0.w};
        const float c1k[4]={C1.x,C1.y,C1.z,C1.w};
        const float f0k[4]={G0.x,G0.y,G0.z,G0.w};
        const float f1k[4]={G1.x,G1.y,G1.z,G1.w};
        const float f2k[4]={G2.x,G2.y,G2.z,G2.w};
        #pragma unroll
        for (int kk=0;kk<4;kk++){
            #pragma unroll
            for (int r=0;r<4;r++){
                float h = fmaxf(fmaf(dm4[r], c1k[kk], c0k[kk]), 0.f);
                t0[r] = fmaf(h, f0k[kk], t0[r]);
                t1[r] = fmaf(h, f1k[kk], t1[r]);
                t2[r] = fmaf(h, f2k[kk], t2[r]);
            }
        }
    }

    const float r2c0=r2s[0], r2c1=r2s[1], r2c2=r2s[2];
    float rgb0=0.f, rgb1=0.f, rgb2=0.f, dep=0.f, ac=0.f;
    #pragma unroll
    for (int r=0;r<4;r++){
        float wvv = wv4[r];
        rgb0 = fmaf(wvv, sigf(t0[r]+r2c0), rgb0);
        rgb1 = fmaf(wvv, sigf(t1[r]+r2c1), rgb1);
        rgb2 = fmaf(wvv, sigf(t2[r]+r2c2), rgb2);
        dep  = fmaf(wvv, dm4[r], dep);
        ac  += wvv;
    }
    #pragma unroll
    for (int o=16;o;o>>=1){
        rgb0 += __shfl_down_sync(FULL, rgb0, o);
        rgb1 += __shfl_down_sync(FULL, rgb1, o);
        rgb2 += __shfl_down_sync(FULL, rgb2, o);
        dep  += __shfl_down_sync(FULL, dep, o);
        ac   += __shfl_down_sync(FULL, ac, o);
    }
    if (lane == 0){
        out[ray*5+0]=rgb0;
        out[ray*5+1]=rgb1;
        out[ray*5+2]=rgb2;
        out[ray*5+3]=dep;
        out[ray*5+4]=ac;
    }
}

extern "C" void kernel_launch(void* const* d_in, const int* in_sizes, int n_in,
                              void* d_out, int out_size)
{
    const float* rays_o = (const float*)d_in[0];
    const float* rays_d = (const float*)d_in[1];
    const float* W1 = (const float*)d_in[2];
    const float* b1 = (const float*)d_in[3];
    const float* W2 = (const float*)d_in[4];
    const float* b2 = (const float*)d_in[5];
    const float* W3 = (const float*)d_in[6];
    const float* b3 = (const float*)d_in[7];
    const float* R1 = (const float*)d_in[8];
    const float* r1 = (const float*)d_in[9];
    const float* R2 = (const float*)d_in[10];
    const float* r2 = (const float*)d_in[11];
    const float* sv = (const float*)d_in[12];
    float* out = (float*)d_out;

    cudaFuncSetAttribute(neus_kernel, cudaFuncAttributeMaxDynamicSharedMemorySize, SMEM_BYTES);
    neus_kernel<<<8192/RAYS, TPB, SMEM_BYTES>>>(rays_o,rays_d,W1,b1,W2,b2,W3,b3,R1,r1,R2,r2,sv,out);
}

// round 10
// speedup vs baseline: 2.9056x; 2.5953x over previous
#include <cuda_runtime.h>
#include <cuda_bf16.h>
#include <math.h>
#include <stdint.h>

#define TPB 512
#define RAYS 16
// B-fragment tiles (bytes): [n(16)][ki(8)][lane(32)] x uint2, hi then lo
#define BF_HI 0
#define BF_LO 32768
// float offsets
#define WSOFF 16384
#define GOFF  (WSOFF + 2056)
#define GSTRIDE 944
#define SMEM_FLOATS (GOFF + RAYS*GSTRIDE)
#define SMEM_BYTES (SMEM_FLOATS*4)

#define O_D    0
#define O_SDF  128
#define O_WB   256
#define O_CDF  384
#define O_DF   516
#define O_SF   532
#define O_DM   548
#define O_C0   676
#define O_C1   804
#define O_AUX  932

__device__ __forceinline__ float sigf(float x){
    return 1.0f/(1.0f + __expf(-x));
}

__device__ __forceinline__ void split2(float h0, float h1, uint32_t& hi, uint32_t& lo){
    __nv_bfloat16 a = __float2bfloat16(h0);
    __nv_bfloat16 b = __float2bfloat16(h1);
    float r0 = h0 - __bfloat162float(a);
    float r1 = h1 - __bfloat162float(b);
    __nv_bfloat16 c = __float2bfloat16(r0);
    __nv_bfloat16 d = __float2bfloat16(r1);
    hi = ((uint32_t)__bfloat16_as_ushort(b)<<16) | (uint32_t)__bfloat16_as_ushort(a);
    lo = ((uint32_t)__bfloat16_as_ushort(d)<<16) | (uint32_t)__bfloat16_as_ushort(c);
}

__device__ __forceinline__ void mma16816(float* c, const uint32_t* a, const uint32_t* b){
    asm volatile(
        "mma.sync.aligned.m16n8k16.row.col.f32.bf16.bf16.f32 "
        "{%0,%1,%2,%3}, {%4,%5,%6,%7}, {%8,%9}, {%0,%1,%2,%3};"
        : "+f"(c[0]), "+f"(c[1]), "+f"(c[2]), "+f"(c[3])
        : "r"(a[0]), "r"(a[1]), "r"(a[2]), "r"(a[3]), "r"(b[0]), "r"(b[1]));
}

// One 16-point SDF MLP batch for THIS warp's ray (warp-private, tensor cores).
// A[16 pts][128 units] x B[128][128], bf16 hi/lo 3-pass, fp32 accum.
__device__ __forceinline__ void mlp_batch16(
    float* __restrict__ G, const char* __restrict__ smc,
    const float* __restrict__ b2s, const float* __restrict__ W3s,
    float b3v, int din_off, int base, int sout_off, int lane)
{
    const float* c0s = G + O_C0;
    const float* c1s = G + O_C1;
    const int r = lane >> 2, m = lane & 3;
    const float d0 = G[din_off + base + r];
    const float d1 = G[din_off + base + r + 8];

    float C[64];
    #pragma unroll
    for (int i=0;i<64;i++) C[i]=0.f;

    #pragma unroll
    for (int ki=0; ki<8; ki++){
        const int j0 = 16*ki + 2*m;
        float c0a=c0s[j0],   c1a=c1s[j0];
        float c0b=c0s[j0+1], c1b=c1s[j0+1];
        float c0c=c0s[j0+8], c1c=c1s[j0+8];
        float c0d=c0s[j0+9], c1d=c1s[j0+9];
        float h00=fmaxf(fmaf(d0,c1a,c0a),0.f), h01=fmaxf(fmaf(d0,c1b,c0b),0.f);
        float h10=fmaxf(fmaf(d1,c1a,c0a),0.f), h11=fmaxf(fmaf(d1,c1b,c0b),0.f);
        float h02=fmaxf(fmaf(d0,c1c,c0c),0.f), h03=fmaxf(fmaf(d0,c1d,c0d),0.f);
        float h12=fmaxf(fmaf(d1,c1c,c0c),0.f), h13=fmaxf(fmaf(d1,c1d,c0d),0.f);
        uint32_t ahi[4], alo[4];
        split2(h00,h01,ahi[0],alo[0]);
        split2(h10,h11,ahi[1],alo[1]);
        split2(h02,h03,ahi[2],alo[2]);
        split2(h12,h13,ahi[3],alo[3]);

        const uint2* bh = (const uint2*)(smc + BF_HI) + ki*32 + lane;
        const uint2* bl = (const uint2*)(smc + BF_LO) + ki*32 + lane;
        #pragma unroll
        for (int n=0;n<16;n++){
            uint2 b_h = bh[n*256];
            uint2 b_l = bl[n*256];
            mma16816(C+n*4, ahi, (const uint32_t*)&b_h);
            mma16816(C+n*4, ahi, (const uint32_t*)&b_l);
            mma16816(C+n*4, alo, (const uint32_t*)&b_h);
        }
    }

    // layer 3: thread owns rows {r, r+8}, cols j = 8n+2m+q
    float t0=0.f, t1=0.f;
    #pragma unroll
    for (int n=0;n<16;n++){
        #pragma unroll
        for (int q=0;q<2;q++){
            int j = 8*n + 2*m + q;
            float bj=b2s[j], wj=W3s[j];
            t0 += fmaxf(C[n*4+q]  +bj,0.f)*wj;
            t1 += fmaxf(C[n*4+2+q]+bj,0.f)*wj;
        }
    }
    t0 += __shfl_xor_sync(0xffffffffu,t0,1);
    t0 += __shfl_xor_sync(0xffffffffu,t0,2);
    t1 += __shfl_xor_sync(0xffffffffu,t1,1);
    t1 += __shfl_xor_sync(0xffffffffu,t1,2);
    if (m==0){
        G[sout_off+base+r]   = t0 + b3v;
        G[sout_off+base+r+8] = t1 + b3v;
    }
    __syncwarp();
}

__global__ void __launch_bounds__(TPB,1) neus_kernel(
    const float* __restrict__ rays_o, const float* __restrict__ rays_d,
    const float* __restrict__ W1, const float* __restrict__ b1,
    const float* __restrict__ W2, const float* __restrict__ b2,
    const float* __restrict__ W3, const float* __restrict__ b3,
    const float* __restrict__ R1, const float* __restrict__ r1,
    const float* __restrict__ R2, const float* __restrict__ r2,
    const float* __restrict__ s_val, float* __restrict__ out)
{
    extern __shared__ __align__(16) float sm[];
    char* smc = (char*)sm;
    float* WS  = sm + WSOFF;
    float* W1s = WS;         // 384
    float* b1s = WS+384;     // 128
    float* b2s = WS+512;     // 128
    float* W3s = WS+640;     // 128
    float* R1s = WS+768;     // 768
    float* r1s = WS+1536;    // 128
    float* F0  = WS+1664;    // 128
    float* F1  = WS+1792;    // 128
    float* F2  = WS+1920;    // 128
    float* r2s = WS+2048;    // 3
    float* b3p = WS+2051;
    float* scp = WS+2052;

    const int tid  = threadIdx.x;
    const int w    = tid >> 5;
    const int lane = tid & 31;
    const int ray  = blockIdx.x*RAYS + w;
    const unsigned FULL = 0xffffffffu;

    // ---- stage W2 as per-lane m16n8k16 B fragments (hi/lo), once per block ----
    for (int s = tid; s < 4096; s += TPB){
        int ln = s & 31, ki = (s>>5)&7, n = s>>8;
        int m2 = ln & 3, col = 8*n + (ln>>2);
        int k0 = 16*ki + 2*m2;
        float w00=W2[k0*128+col],     w01=W2[(k0+1)*128+col];
        float w10=W2[(k0+8)*128+col], w11=W2[(k0+9)*128+col];
        uint32_t h0,l0,h1,l1;
        split2(w00,w01,h0,l0);
        split2(w10,w11,h1,l1);
        ((uint2*)(smc+BF_HI))[s] = make_uint2(h0,h1);
        ((uint2*)(smc+BF_LO))[s] = make_uint2(l0,l1);
    }
    for (int idx=tid; idx<384; idx+=TPB) W1s[idx] = W1[idx];
    for (int idx=tid; idx<128; idx+=TPB){
        b1s[idx]=b1[idx]; b2s[idx]=b2[idx]; W3s[idx]=W3[idx]; r1s[idx]=r1[idx];
        F0[idx]=R2[3*idx]; F1[idx]=R2[3*idx+1]; F2[idx]=R2[3*idx+2];
    }
    for (int idx=tid; idx<768; idx+=TPB) R1s[idx] = R1[idx];
    if (tid < 3) r2s[tid] = r2[tid];
    if (tid == 0){ b3p[0] = b3[0]; scp[0] = s_val[0]*64.0f; }
    __syncthreads();

    float* G = sm + GOFF + w*GSTRIDE;
    const float b3v = b3p[0];

    if (lane == 0){
        float oxl=rays_o[ray*3+0], oyl=rays_o[ray*3+1], ozl=rays_o[ray*3+2];
        float ddx=rays_d[ray*3+0], ddy=rays_d[ray*3+1], ddz=rays_d[ray*3+2];
        float nrm = sqrtf(ddx*ddx+ddy*ddy+ddz*ddz);
        G[O_AUX+0]=oxl; G[O_AUX+1]=oyl; G[O_AUX+2]=ozl;
        G[O_AUX+3]=ddx/nrm; G[O_AUX+4]=ddy/nrm; G[O_AUX+5]=ddz/nrm;
    }
    #pragma unroll
    for (int e=lane; e<64; e+=32){
        float t = (e==63) ? 1.0f : (float)e * (1.0f/63.0f);
        G[O_D + e] = 0.5f*(1.0f-t) + 4.0f*t;
    }
    __syncwarp();

    const float ox=G[O_AUX+0], oy=G[O_AUX+1], oz=G[O_AUX+2];
    const float dx=G[O_AUX+3], dy=G[O_AUX+4], dz=G[O_AUX+5];

    // per-ray layer-1 coefficients staged in smem
    #pragma unroll
    for (int u=0; u<4; u++){
        int j = lane + 32*u;
        float wx=W1s[j], wy=W1s[128+j], wz=W1s[256+j];
        G[O_C1+j] = dx*wx + dy*wy + dz*wz;
        G[O_C0+j] = b1s[j] + ox*wx + oy*wy + oz*wz;
    }
    __syncwarp();

    // ---- coarse SDF: 4 x 16-pt batches ----
    for (int b=0;b<4;b++)
        mlp_batch16(G, smc, b2s, W3s, b3v, O_D, b*16, O_SDF, lane);

    // ---- hierarchical upsampling ----
    int n = 64;
    for (int it=0; it<4; it++){
        float s_i = 64.0f * (float)(1<<it);
        #pragma unroll
        for (int e=lane; e<128; e+=32){
            float val = 0.0f;
            if (e < n-1){
                float psdf=G[O_SDF+e], nsdf=G[O_SDF+e+1], pz=G[O_D+e], nz=G[O_D+e+1];
                float dot = (nsdf-psdf)/(nz-pz+1e-5f);
                float pdot = 0.0f;
                if (e > 0){
                    float ppsdf=G[O_SDF+e-1], ppz=G[O_D+e-1];
                    pdot = (psdf-ppsdf)/(pz-ppz+1e-5f);
                }
                float dc = fminf(fmaxf(fminf(pdot,dot),-10.0f),0.0f);
                float mid = 0.5f*(psdf+nsdf), dist = nz-pz;
                float pc = sigf((mid - dc*dist*0.5f)*s_i);
                float nc = sigf((mid + dc*dist*0.5f)*s_i);
                val = (pc-nc+1e-5f)/(pc+1e-5f);
            }
            G[O_WB+e] = val;
        }
        __syncwarp();

        // warp scan: w = a*T + 1e-5 ; cdf = cumsum(w)/sum
        {
            float4 av = *(const float4*)(G + O_WB + 4*lane);
            float a[4] = {av.x, av.y, av.z, av.w};
            float sh[4], Tl[4], wv4[4];
            #pragma unroll
            for (int q=0;q<4;q++){
                int e = 4*lane + q;
                sh[q] = (e < n-1) ? (1.0f - a[q] + 1e-10f) : 1.0f;
            }
            Tl[0]=1.0f; Tl[1]=sh[0]; Tl[2]=sh[0]*sh[1]; Tl[3]=Tl[2]*sh[2];
            float P = Tl[3]*sh[3];
            float v = P;
            #pragma unroll
            for (int o=1;o<32;o<<=1){
                float t = __shfl_up_sync(FULL, v, o);
                if (lane >= o) v *= t;
            }
            float exc = __shfl_up_sync(FULL, v, 1);
            if (lane == 0) exc = 1.0f;
            float lsum = 0.f;
            #pragma unroll
            for (int q=0;q<4;q++){
                int e = 4*lane + q;
                wv4[q] = (e < n-1) ? fmaf(a[q], exc*Tl[q], 1e-5f) : 0.0f;
                lsum += wv4[q];
            }
            float va = lsum;
            #pragma unroll
            for (int o=1;o<32;o<<=1){
                float t = __shfl_up_sync(FULL, va, o);
                if (lane >= o) va += t;
            }
            float total = __shfl_sync(FULL, va, 31);
            float inv = 1.0f/total;
            float basec = va - lsum;
            float run = 0.f;
            #pragma unroll
            for (int q=0;q<4;q++){
                run += wv4[q];
                G[O_CDF + 4*lane + 1 + q] = (basec + run)*inv;
            }
            if (lane == 0) G[O_CDF] = 0.0f;
        }
        __syncwarp();

        if (lane < 16){
            float u = (lane==15) ? 1.0f : (float)lane * (1.0f/15.0f);
            int lo = 0, hi = n;
            #pragma unroll
            for (int s7=0; s7<7; s7++){
                int mid = (lo+hi) >> 1;
                if (G[O_CDF+mid] <= u) lo = mid+1; else hi = mid;
            }
            int ind = lo;
            int below = ind-1; if (below < 0) below = 0; if (below > n-1) below = n-1;
            int above = (ind < n-1) ? ind : n-1;
            float cb=G[O_CDF+below], ca=G[O_CDF+above];
            float bb=G[O_D+below],  ba=G[O_D+above];
            float den = ca-cb; if (den < 1e-5f) den = 1.0f;
            float tt = (u-cb)/den;
            G[O_DF+lane] = bb + tt*(ba-bb);
        }
        __syncwarp();

        // one 16-pt fine batch
        mlp_batch16(G, smc, b2s, W3s, b3v, O_DF, 0, O_SF, lane);

        // ---- parallel stable merge via ranks ----
        {
            float dv[4], sv[4]; int rk[4];
            #pragma unroll
            for (int mm=0;mm<4;mm++){
                int e = lane + 32*mm;
                rk[mm] = -1;
                if (e < n){
                    dv[mm]=G[O_D+e]; sv[mm]=G[O_SDF+e];
                    int lo=0, hi=16;
                    #pragma unroll
                    for (int s5=0;s5<5;s5++){
                        int mid=(lo+hi)>>1;
                        if (mid < 16 && G[O_DF+mid] < dv[mm]) lo=mid+1; else hi=mid;
                    }
                    rk[mm] = e + lo;
                }
            }
            float bf=0.f, bsf=0.f; int rkf=-1;
            if (lane < 16){
                bf=G[O_DF+lane]; bsf=G[O_SF+lane];
                int lo=0, hi=n;
                #pragma unroll
                for (int s7=0;s7<7;s7++){
                    int mid=(lo+hi)>>1;
                    if (mid < n && G[O_D+mid] <= bf) lo=mid+1; else hi=mid;
                }
                rkf = lane + lo;
            }
            __syncwarp();
            #pragma unroll
            for (int mm=0;mm<4;mm++){
                if (rk[mm] >= 0){ G[O_D+rk[mm]]=dv[mm]; G[O_SDF+rk[mm]]=sv[mm]; }
            }
            if (rkf >= 0){ G[O_D+rkf]=bf; G[O_SDF+rkf]=bsf; }
        }
        __syncwarp();
        n += 16;
    }

    // ---- final compositing (n==128) ----
    const float s = scp[0];
    #pragma unroll
    for (int e=lane; e<128; e+=32) G[O_CDF+e] = sigf(G[O_SDF+e]*s);
    #pragma unroll
    for (int e=lane; e<128; e+=32) G[O_DM+e] = (e<127) ? 0.5f*(G[O_D+e]+G[O_D+e+1]) : 0.0f;
    __syncwarp();
    #pragma unroll
    for (int e=lane; e<128; e+=32){
        float val = 0.0f;
        if (e < 127){
            float a = (G[O_CDF+e]-G[O_CDF+e+1]+1e-5f)/(G[O_CDF+e]+1e-5f);
            val = fminf(fmaxf(a,0.0f),1.0f);
        }
        G[O_WB+e] = val;
    }
    __syncwarp();

    float wv4[4], dm4[4];
    {
        float4 av = *(const float4*)(G + O_WB + 4*lane);
        float4 dmv= *(const float4*)(G + O_DM + 4*lane);
        float a[4] = {av.x, av.y, av.z, av.w};
        dm4[0]=dmv.x; dm4[1]=dmv.y; dm4[2]=dmv.z; dm4[3]=dmv.w;
        float sh[4], Tl[4];
        #pragma unroll
        for (int q=0;q<4;q++){
            int e = 4*lane + q;
            sh[q] = (e < 127) ? (1.0f - a[q] + 1e-10f) : 1.0f;
        }
        Tl[0]=1.0f; Tl[1]=sh[0]; Tl[2]=sh[0]*sh[1]; Tl[3]=Tl[2]*sh[2];
        float P = Tl[3]*sh[3];
        float v = P;
        #pragma unroll
        for (int o=1;o<32;o<<=1){
            float t = __shfl_up_sync(FULL, v, o);
            if (lane >= o) v *= t;
        }
        float exc = __shfl_up_sync(FULL, v, 1);
        if (lane == 0) exc = 1.0f;
        #pragma unroll
        for (int q=0;q<4;q++){
            int e = 4*lane + q;
            wv4[q] = (e < 127) ? a[q]*exc*Tl[q] : 0.0f;
        }
    }

    // ---- radiance: per-ray coeffs staged (reuse O_C0/O_C1), flipped loop ----
    float* A0 = G + O_C0;
    float* A1 = G + O_C1;
    #pragma unroll
    for (int u=0; u<4; u++){
        int j = lane + 32*u;
        float c1r = dx*R1s[j] + dy*R1s[128+j] + dz*R1s[256+j];
        float c0r = r1s[j] + ox*R1s[j] + oy*R1s[128+j] + oz*R1s[256+j]
                  + dx*R1s[384+j] + dy*R1s[512+j] + dz*R1s[640+j];
        A0[j]=c0r; A1[j]=c1r;
    }
    __syncwarp();

    float t0[4]={0,0,0,0}, t1[4]={0,0,0,0}, t2[4]={0,0,0,0};
    #pragma unroll 2
    for (int k4=0; k4<32; k4++){
        float4 C0=*(const float4*)(A0+4*k4);
        float4 C1=*(const float4*)(A1+4*k4);
        float4 G0=*(const float4*)(F0+4*k4);
        float4 G1=*(const float4*)(F1+4*k4);
        float4 G2=*(const float4*)(F2+4*k4);
        const float c0k[4]={C0.x,C0.y,C0.z,C0.w};
        const float c1k[4]={C1.x,C1.y,C1.z,C1.w};
        const float f0k[4]={G0.x,G0.y,G0.z,G0.w};
        const float f1k[4]={G1.x,G1.y,G1.z,G1.w};
        const float f2k[4]={G2.x,G2.y,G2.z,G2.w};
        #pragma unroll
        for (int kk=0;kk<4;kk++){
            #pragma unroll
            for (int q=0;q<4;q++){
                float h = fmaxf(fmaf(dm4[q], c1k[kk], c0k[kk]), 0.f);
                t0[q] = fmaf(h, f0k[kk], t0[q]);
                t1[q] = fmaf(h, f1k[kk], t1[q]);
                t2[q] = fmaf(h, f2k[kk], t2[q]);
            }
        }
    }

    const float r2c0=r2s[0], r2c1=r2s[1], r2c2=r2s[2];
    float rgb0=0.f, rgb1=0.f, rgb2=0.f, dep=0.f, ac=0.f;
    #pragma unroll
    for (int q=0;q<4;q++){
        float wvv = wv4[q];
        rgb0 = fmaf(wvv, sigf(t0[q]+r2c0), rgb0);
        rgb1 = fmaf(wvv, sigf(t1[q]+r2c1), rgb1);
        rgb2 = fmaf(wvv, sigf(t2[q]+r2c2), rgb2);
        dep  = fmaf(wvv, dm4[q], dep);
        ac  += wvv;
    }
    #pragma unroll
    for (int o=16;o;o>>=1){
        rgb0 += __shfl_down_sync(FULL, rgb0, o);
        rgb1 += __shfl_down_sync(FULL, rgb1, o);
        rgb2 += __shfl_down_sync(FULL, rgb2, o);
        dep  += __shfl_down_sync(FULL, dep, o);
        ac   += __shfl_down_sync(FULL, ac, o);
    }
    if (lane == 0){
        out[ray*5+0]=rgb0;
        out[ray*5+1]=rgb1;
        out[ray*5+2]=rgb2;
        out[ray*5+3]=dep;
        out[ray*5+4]=ac;
    }
}

extern "C" void kernel_launch(void* const* d_in, const int* in_sizes, int n_in,
                              void* d_out, int out_size)
{
    const float* rays_o = (const float*)d_in[0];
    const float* rays_d = (const float*)d_in[1];
    const float* W1 = (const float*)d_in[2];
    const float* b1 = (const float*)d_in[3];
    const float* W2 = (const float*)d_in[4];
    const float* b2 = (const float*)d_in[5];
    const float* W3 = (const float*)d_in[6];
    const float* b3 = (const float*)d_in[7];
    const float* R1 = (const float*)d_in[8];
    const float* r1 = (const float*)d_in[9];
    const float* R2 = (const float*)d_in[10];
    const float* r2 = (const float*)d_in[11];
    const float* sv = (const float*)d_in[12];
    float* out = (float*)d_out;

    cudaFuncSetAttribute(neus_kernel, cudaFuncAttributeMaxDynamicSharedMemorySize, SMEM_BYTES);
    neus_kernel<<<8192/RAYS, TPB, SMEM_BYTES>>>(rays_o,rays_d,W1,b1,W2,b2,W3,b3,R1,r1,R2,r2,sv,out);
}

// round 11
// speedup vs baseline: 2.9798x; 1.0255x over previous
#include <cuda_runtime.h>
#include <cuda_bf16.h>
#include <math.h>
#include <stdint.h>

#define TPB 512
#define RAYS 16
// smem bytes: [0,64K) B fragments uint4{bhi0,bhi1,blo0,blo1}; [64K,72K) layer3 pairs
#define BW_OFF 65536
// float offsets
#define WSOFF 18432
#define GOFF  (WSOFF + 2056)
#define GSTRIDE 944
#define SMEM_FLOATS (GOFF + RAYS*GSTRIDE)
#define SMEM_BYTES (SMEM_FLOATS*4)

#define O_D    0
#define O_SDF  128
#define O_WB   256
#define O_CDF  384
#define O_DF   516
#define O_SF   532
#define O_DM   548
#define O_C0   676
#define O_C1   804
#define O_AUX  932

__device__ __forceinline__ float sigf(float x){
    return 1.0f/(1.0f + __expf(-x));
}

// pack two floats to bf16x2 (h1 upper, h0 lower) + bf16x2 residual, 6 ops
__device__ __forceinline__ void fsplit2(float h0, float h1, uint32_t& hi, uint32_t& lo){
    uint32_t h;
    asm("cvt.rn.bf16x2.f32 %0, %1, %2;" : "=r"(h) : "f"(h1), "f"(h0));
    float e0 = __uint_as_float(h << 16);
    float e1 = __uint_as_float(h & 0xFFFF0000u);
    uint32_t l;
    asm("cvt.rn.bf16x2.f32 %0, %1, %2;" : "=r"(l) : "f"(h1 - e1), "f"(h0 - e0));
    hi = h; lo = l;
}

__device__ __forceinline__ void mma16816(float* c, const uint32_t* a, const uint32_t* b){
    asm volatile(
        "mma.sync.aligned.m16n8k16.row.col.f32.bf16.bf16.f32 "
        "{%0,%1,%2,%3}, {%4,%5,%6,%7}, {%8,%9}, {%0,%1,%2,%3};"
        : "+f"(c[0]), "+f"(c[1]), "+f"(c[2]), "+f"(c[3])
        : "r"(a[0]), "r"(a[1]), "r"(a[2]), "r"(a[3]), "r"(b[0]), "r"(b[1]));
}

// One 16-point SDF MLP batch for THIS warp's ray (warp-private, tensor cores).
// n-loop split into 2 halves (C[32] regs); A fragments rebuilt per half.
__device__ __forceinline__ void mlp_batch16(
    float* __restrict__ G, const char* __restrict__ smc,
    float b3v, int din_off, int base, int sout_off, int lane)
{
    const float* c0s = G + O_C0;
    const float* c1s = G + O_C1;
    const int r = lane >> 2, m = lane & 3;
    const float d0 = G[din_off + base + r];
    const float d1 = G[din_off + base + r + 8];
    float t0 = 0.f, t1 = 0.f;

    #pragma unroll
    for (int half=0; half<2; half++){
        float C[32];
        #pragma unroll
        for (int i=0;i<32;i++) C[i]=0.f;

        #pragma unroll
        for (int ki=0; ki<8; ki++){
            const int j0 = 16*ki + 2*m;
            float2 ca = *(const float2*)(c0s + j0);
            float2 cb = *(const float2*)(c1s + j0);
            float2 cc = *(const float2*)(c0s + j0 + 8);
            float2 cd = *(const float2*)(c1s + j0 + 8);
            float h00=fmaxf(fmaf(d0,cb.x,ca.x),0.f), h01=fmaxf(fmaf(d0,cb.y,ca.y),0.f);
            float h10=fmaxf(fmaf(d1,cb.x,ca.x),0.f), h11=fmaxf(fmaf(d1,cb.y,ca.y),0.f);
            float h02=fmaxf(fmaf(d0,cd.x,cc.x),0.f), h03=fmaxf(fmaf(d0,cd.y,cc.y),0.f);
            float h12=fmaxf(fmaf(d1,cd.x,cc.x),0.f), h13=fmaxf(fmaf(d1,cd.y,cc.y),0.f);
            uint32_t ahi[4], alo[4];
            fsplit2(h00,h01,ahi[0],alo[0]);
            fsplit2(h10,h11,ahi[1],alo[1]);
            fsplit2(h02,h03,ahi[2],alo[2]);
            fsplit2(h12,h13,ahi[3],alo[3]);

            const uint4* bp = (const uint4*)smc + half*2048 + ki*32 + lane;
            #pragma unroll
            for (int n=0;n<8;n++){
                uint4 b = bp[n*256];
                mma16816(C+n*4, ahi, &b.x);
                mma16816(C+n*4, ahi, &b.z);
                mma16816(C+n*4, alo, &b.x);
            }
        }

        #pragma unroll
        for (int n=0;n<8;n++){
            int ng = half*8 + n;
            float4 bw = *(const float4*)(smc + BW_OFF + (ng*32+lane)*16);
            t0 += fmaxf(C[n*4+0]+bw.x,0.f)*bw.y + fmaxf(C[n*4+1]+bw.z,0.f)*bw.w;
            t1 += fmaxf(C[n*4+2]+bw.x,0.f)*bw.y + fmaxf(C[n*4+3]+bw.z,0.f)*bw.w;
        }
    }

    t0 += __shfl_xor_sync(0xffffffffu,t0,1);
    t0 += __shfl_xor_sync(0xffffffffu,t0,2);
    t1 += __shfl_xor_sync(0xffffffffu,t1,1);
    t1 += __shfl_xor_sync(0xffffffffu,t1,2);
    if (m==0){
        G[sout_off+base+r]   = t0 + b3v;
        G[sout_off+base+r+8] = t1 + b3v;
    }
    __syncwarp();
}

__global__ void __launch_bounds__(TPB,1) neus_kernel(
    const float* __restrict__ rays_o, const float* __restrict__ rays_d,
    const float* __restrict__ W1, const float* __restrict__ b1,
    const float* __restrict__ W2, const float* __restrict__ b2,
    const float* __restrict__ W3, const float* __restrict__ b3,
    const float* __restrict__ R1, const float* __restrict__ r1,
    const float* __restrict__ R2, const float* __restrict__ r2,
    const float* __restrict__ s_val, float* __restrict__ out)
{
    extern __shared__ __align__(16) float sm[];
    char* smc = (char*)sm;
    float* WS  = sm + WSOFF;
    float* W1s = WS;         // 384
    float* b1s = WS+384;     // 128
    float* R1s = WS+768;     // 768
    float* r1s = WS+1536;    // 128
    float* F0  = WS+1664;    // 128
    float* F1  = WS+1792;    // 128
    float* F2  = WS+1920;    // 128
    float* r2s = WS+2048;    // 3
    float* b3p = WS+2051;
    float* scp = WS+2052;

    const int tid  = threadIdx.x;
    const int w    = tid >> 5;
    const int lane = tid & 31;
    const int ray  = blockIdx.x*RAYS + w;
    const unsigned FULL = 0xffffffffu;

    // ---- stage W2 as interleaved hi/lo m16n8k16 B fragments (uint4), once ----
    for (int s = tid; s < 4096; s += TPB){
        int ln = s & 31, ki = (s>>5)&7, n = s>>8;
        int m2 = ln & 3, col = 8*n + (ln>>2);
        int k0 = 16*ki + 2*m2;
        float w00=W2[k0*128+col],     w01=W2[(k0+1)*128+col];
        float w10=W2[(k0+8)*128+col], w11=W2[(k0+9)*128+col];
        uint32_t h0,l0,h1,l1;
        fsplit2(w00,w01,h0,l0);
        fsplit2(w10,w11,h1,l1);
        ((uint4*)smc)[s] = make_uint4(h0,h1,l0,l1);
    }
    // ---- stage layer-3 (b2,W3) fragment pairs ----
    for (int s = tid; s < 512; s += TPB){
        int ln = s & 31, n = s >> 5;
        int j0 = 8*n + 2*(ln & 3);
        ((float4*)(smc+BW_OFF))[s] = make_float4(b2[j0], W3[j0], b2[j0+1], W3[j0+1]);
    }
    for (int idx=tid; idx<384; idx+=TPB) W1s[idx] = W1[idx];
    for (int idx=tid; idx<128; idx+=TPB){
        b1s[idx]=b1[idx]; r1s[idx]=r1[idx];
        F0[idx]=R2[3*idx]; F1[idx]=R2[3*idx+1]; F2[idx]=R2[3*idx+2];
    }
    for (int idx=tid; idx<768; idx+=TPB) R1s[idx] = R1[idx];
    if (tid < 3) r2s[tid] = r2[tid];
    if (tid == 0){ b3p[0] = b3[0]; scp[0] = s_val[0]*64.0f; }
    __syncthreads();

    float* G = sm + GOFF + w*GSTRIDE;
    const float b3v = b3p[0];

    if (lane == 0){
        float oxl=rays_o[ray*3+0], oyl=rays_o[ray*3+1], ozl=rays_o[ray*3+2];
        float ddx=rays_d[ray*3+0], ddy=rays_d[ray*3+1], ddz=rays_d[ray*3+2];
        float nrm = sqrtf(ddx*ddx+ddy*ddy+ddz*ddz);
        G[O_AUX+0]=oxl; G[O_AUX+1]=oyl; G[O_AUX+2]=ozl;
        G[O_AUX+3]=ddx/nrm; G[O_AUX+4]=ddy/nrm; G[O_AUX+5]=ddz/nrm;
    }
    #pragma unroll
    for (int e=lane; e<64; e+=32){
        float t = (e==63) ? 1.0f : (float)e * (1.0f/63.0f);
        G[O_D + e] = 0.5f*(1.0f-t) + 4.0f*t;
    }
    __syncwarp();

    const float ox=G[O_AUX+0], oy=G[O_AUX+1], oz=G[O_AUX+2];
    const float dx=G[O_AUX+3], dy=G[O_AUX+4], dz=G[O_AUX+5];

    // per-ray layer-1 coefficients staged in smem
    #pragma unroll
    for (int u=0; u<4; u++){
        int j = lane + 32*u;
        float wx=W1s[j], wy=W1s[128+j], wz=W1s[256+j];
        G[O_C1+j] = dx*wx + dy*wy + dz*wz;
        G[O_C0+j] = b1s[j] + ox*wx + oy*wy + oz*wz;
    }
    __syncwarp();

    // ---- coarse SDF: 4 x 16-pt batches ----
    for (int b=0;b<4;b++)
        mlp_batch16(G, smc, b3v, O_D, b*16, O_SDF, lane);

    // ---- hierarchical upsampling ----
    int n = 64;
    for (int it=0; it<4; it++){
        float s_i = 64.0f * (float)(1<<it);
        #pragma unroll
        for (int e=lane; e<128; e+=32){
            float val = 0.0f;
            if (e < n-1){
                float psdf=G[O_SDF+e], nsdf=G[O_SDF+e+1], pz=G[O_D+e], nz=G[O_D+e+1];
                float dot = (nsdf-psdf)/(nz-pz+1e-5f);
                float pdot = 0.0f;
                if (e > 0){
                    float ppsdf=G[O_SDF+e-1], ppz=G[O_D+e-1];
                    pdot = (psdf-ppsdf)/(pz-ppz+1e-5f);
                }
                float dc = fminf(fmaxf(fminf(pdot,dot),-10.0f),0.0f);
                float mid = 0.5f*(psdf+nsdf), dist = nz-pz;
                float pc = sigf((mid - dc*dist*0.5f)*s_i);
                float nc = sigf((mid + dc*dist*0.5f)*s_i);
                val = (pc-nc+1e-5f)/(pc+1e-5f);
            }
            G[O_WB+e] = val;
        }
        __syncwarp();

        // warp scan: w = a*T + 1e-5 ; cdf = cumsum(w)/sum
        {
            float4 av = *(const float4*)(G + O_WB + 4*lane);
            float a[4] = {av.x, av.y, av.z, av.w};
            float sh[4], Tl[4], wv4[4];
            #pragma unroll
            for (int q=0;q<4;q++){
                int e = 4*lane + q;
                sh[q] = (e < n-1) ? (1.0f - a[q] + 1e-10f) : 1.0f;
            }
            Tl[0]=1.0f; Tl[1]=sh[0]; Tl[2]=sh[0]*sh[1]; Tl[3]=Tl[2]*sh[2];
            float P = Tl[3]*sh[3];
            float v = P;
            #pragma unroll
            for (int o=1;o<32;o<<=1){
                float t = __shfl_up_sync(FULL, v, o);
                if (lane >= o) v *= t;
            }
            float exc = __shfl_up_sync(FULL, v, 1);
            if (lane == 0) exc = 1.0f;
            float lsum = 0.f;
            #pragma unroll
            for (int q=0;q<4;q++){
                int e = 4*lane + q;
                wv4[q] = (e < n-1) ? fmaf(a[q], exc*Tl[q], 1e-5f) : 0.0f;
                lsum += wv4[q];
            }
            float va = lsum;
            #pragma unroll
            for (int o=1;o<32;o<<=1){
                float t = __shfl_up_sync(FULL, va, o);
                if (lane >= o) va += t;
            }
            float total = __shfl_sync(FULL, va, 31);
            float inv = 1.0f/total;
            float basec = va - lsum;
            float run = 0.f;
            #pragma unroll
            for (int q=0;q<4;q++){
                run += wv4[q];
                G[O_CDF + 4*lane + 1 + q] = (basec + run)*inv;
            }
            if (lane == 0) G[O_CDF] = 0.0f;
        }
        __syncwarp();

        if (lane < 16){
            float u = (lane==15) ? 1.0f : (float)lane * (1.0f/15.0f);
            int lo = 0, hi = n;
            #pragma unroll
            for (int s7=0; s7<7; s7++){
                int mid = (lo+hi) >> 1;
                if (G[O_CDF+mid] <= u) lo = mid+1; else hi = mid;
            }
            int ind = lo;
            int below = ind-1; if (below < 0) below = 0; if (below > n-1) below = n-1;
            int above = (ind < n-1) ? ind : n-1;
            float cb=G[O_CDF+below], ca=G[O_CDF+above];
            float bb=G[O_D+below],  ba=G[O_D+above];
            float den = ca-cb; if (den < 1e-5f) den = 1.0f;
            float tt = (u-cb)/den;
            G[O_DF+lane] = bb + tt*(ba-bb);
        }
        __syncwarp();

        // one 16-pt fine batch
        mlp_batch16(G, smc, b3v, O_DF, 0, O_SF, lane);

        // ---- parallel stable merge via ranks ----
        {
            float dv[4], sv[4]; int rk[4];
            #pragma unroll
            for (int mm=0;mm<4;mm++){
                int e = lane + 32*mm;
                rk[mm] = -1;
                if (e < n){
                    dv[mm]=G[O_D+e]; sv[mm]=G[O_SDF+e];
                    int lo=0, hi=16;
                    #pragma unroll
                    for (int s5=0;s5<5;s5++){
                        int mid=(lo+hi)>>1;
                        if (mid < 16 && G[O_DF+mid] < dv[mm]) lo=mid+1; else hi=mid;
                    }
                    rk[mm] = e + lo;
                }
            }
            float bf=0.f, bsf=0.f; int rkf=-1;
            if (lane < 16){
                bf=G[O_DF+lane]; bsf=G[O_SF+lane];
                int lo=0, hi=n;
                #pragma unroll
                for (int s7=0;s7<7;s7++){
                    int mid=(lo+hi)>>1;
                    if (mid < n && G[O_D+mid] <= bf) lo=mid+1; else hi=mid;
                }
                rkf = lane + lo;
            }
            __syncwarp();
            #pragma unroll
            for (int mm=0;mm<4;mm++){
                if (rk[mm] >= 0){ G[O_D+rk[mm]]=dv[mm]; G[O_SDF+rk[mm]]=sv[mm]; }
            }
            if (rkf >= 0){ G[O_D+rkf]=bf; G[O_SDF+rkf]=bsf; }
        }
        __syncwarp();
        n += 16;
    }

    // ---- final compositing (n==128) ----
    const float s = scp[0];
    #pragma unroll
    for (int e=lane; e<128; e+=32) G[O_CDF+e] = sigf(G[O_SDF+e]*s);
    #pragma unroll
    for (int e=lane; e<128; e+=32) G[O_DM+e] = (e<127) ? 0.5f*(G[O_D+e]+G[O_D+e+1]) : 0.0f;
    __syncwarp();
    #pragma unroll
    for (int e=lane; e<128; e+=32){
        float val = 0.0f;
        if (e < 127){
            float a = (G[O_CDF+e]-G[O_CDF+e+1]+1e-5f)/(G[O_CDF+e]+1e-5f);
            val = fminf(fmaxf(a,0.0f),1.0f);
        }
        G[O_WB+e] = val;
    }
    __syncwarp();

    float wv4[4], dm4[4];
    {
        float4 av = *(const float4*)(G + O_WB + 4*lane);
        float4 dmv= *(const float4*)(G + O_DM + 4*lane);
        float a[4] = {av.x, av.y, av.z, av.w};
        dm4[0]=dmv.x; dm4[1]=dmv.y; dm4[2]=dmv.z; dm4[3]=dmv.w;
        float sh[4], Tl[4];
        #pragma unroll
        for (int q=0;q<4;q++){
            int e = 4*lane + q;
            sh[q] = (e < 127) ? (1.0f - a[q] + 1e-10f) : 1.0f;
        }
        Tl[0]=1.0f; Tl[1]=sh[0]; Tl[2]=sh[0]*sh[1]; Tl[3]=Tl[2]*sh[2];
        float P = Tl[3]*sh[3];
        float v = P;
        #pragma unroll
        for (int o=1;o<32;o<<=1){
            float t = __shfl_up_sync(FULL, v, o);
            if (lane >= o) v *= t;
        }
        float exc = __shfl_up_sync(FULL, v, 1);
        if (lane == 0) exc = 1.0f;
        #pragma unroll
        for (int q=0;q<4;q++){
            int e = 4*lane + q;
            wv4[q] = (e < 127) ? a[q]*exc*Tl[q] : 0.0f;
        }
    }

    // ---- radiance: per-ray coeffs staged (reuse O_C0/O_C1), flipped loop ----
    float* A0 = G + O_C0;
    float* A1 = G + O_C1;
    #pragma unroll
    for (int u=0; u<4; u++){
        int j = lane + 32*u;
        float c1r = dx*R1s[j] + dy*R1s[128+j] + dz*R1s[256+j];
        float c0r = r1s[j] + ox*R1s[j] + oy*R1s[128+j] + oz*R1s[256+j]
                  + dx*R1s[384+j] + dy*R1s[512+j] + dz*R1s[640+j];
        A0[j]=c0r; A1[j]=c1r;
    }
    __syncwarp();

    float t0[4]={0,0,0,0}, t1[4]={0,0,0,0}, t2[4]={0,0,0,0};
    #pragma unroll 2
    for (int k4=0; k4<32; k4++){
        float4 C0=*(const float4*)(A0+4*k4);
        float4 C1=*(const float4*)(A1+4*k4);
        float4 G0=*(const float4*)(F0+4*k4);
        float4 G1=*(const float4*)(F1+4*k4);
        float4 G2=*(const float4*)(F2+4*k4);
        const float c0k[4]={C0.x,C0.y,C0.z,C0.w};
        const float c1k[4]={C1.x,C1.y,C1.z,C1.w};
        const float f0k[4]={G0.x,G0.y,G0.z,G0.w};
        const float f1k[4]={G1.x,G1.y,G1.z,G1.w};
        const float f2k[4]={G2.x,G2.y,G2.z,G2.w};
        #pragma unroll
        for (int kk=0;kk<4;kk++){
            #pragma unroll
            for (int q=0;q<4;q++){
                float h = fmaxf(fmaf(dm4[q], c1k[kk], c0k[kk]), 0.f);
                t0[q] = fmaf(h, f0k[kk], t0[q]);
                t1[q] = fmaf(h, f1k[kk], t1[q]);
                t2[q] = fmaf(h, f2k[kk], t2[q]);
            }
        }
    }

    const float r2c0=r2s[0], r2c1=r2s[1], r2c2=r2s[2];
    float rgb0=0.f, rgb1=0.f, rgb2=0.f, dep=0.f, ac=0.f;
    #pragma unroll
    for (int q=0;q<4;q++){
        float wvv = wv4[q];
        rgb0 = fmaf(wvv, sigf(t0[q]+r2c0), rgb0);
        rgb1 = fmaf(wvv, sigf(t1[q]+r2c1), rgb1);
        rgb2 = fmaf(wvv, sigf(t2[q]+r2c2), rgb2);
        dep  = fmaf(wvv, dm4[q], dep);
        ac  += wvv;
    }
    #pragma unroll
    for (int o=16;o;o>>=1){
        rgb0 += __shfl_down_sync(FULL, rgb0, o);
        rgb1 += __shfl_down_sync(FULL, rgb1, o);
        rgb2 += __shfl_down_sync(FULL, rgb2, o);
        dep  += __shfl_down_sync(FULL, dep, o);
        ac   += __shfl_down_sync(FULL, ac, o);
    }
    if (lane == 0){
        out[ray*5+0]=rgb0;
        out[ray*5+1]=rgb1;
        out[ray*5+2]=rgb2;
        out[ray*5+3]=dep;
        out[ray*5+4]=ac;
    }
}

extern "C" void kernel_launch(void* const* d_in, const int* in_sizes, int n_in,
                              void* d_out, int out_size)
{
    const float* rays_o = (const float*)d_in[0];
    const float* rays_d = (const float*)d_in[1];
    const float* W1 = (const float*)d_in[2];
    const float* b1 = (const float*)d_in[3];
    const float* W2 = (const float*)d_in[4];
    const float* b2 = (const float*)d_in[5];
    const float* W3 = (const float*)d_in[6];
    const float* b3 = (const float*)d_in[7];
    const float* R1 = (const float*)d_in[8];
    const float* r1 = (const float*)d_in[9];
    const float* R2 = (const float*)d_in[10];
    const float* r2 = (const float*)d_in[11];
    const float* sv = (const float*)d_in[12];
    float* out = (float*)d_out;

    cudaFuncSetAttribute(neus_kernel, cudaFuncAttributeMaxDynamicSharedMemorySize, SMEM_BYTES);
    neus_kernel<<<8192/RAYS, TPB, SMEM_BYTES>>>(rays_o,rays_d,W1,b1,W2,b2,W3,b3,R1,r1,R2,r2,sv,out);
}